// round 9
// baseline (speedup 1.0000x reference)
#include <cuda_runtime.h>
#include <cstdint>

// ============================================================================
// GroupFC: out[32768,1024] = data @ W^T + b (fp32), mma.sync tf32 (sm_103).
// R9: break the smem-bandwidth floor.
//  - Warp tiles 128x32 (warp owns a 32-col slab): B fragments unique per warp
//    -> B read DIRECTLY from L2 (g_W, RNA-pre-rounded) via LDG.64 with
//    whole-chunk register prefetch; B never touches smem.
//  - A staged in smem (3-stage cp.async, 16KB/stage, 32B-granular swizzle,
//    conflict-free LDS.64), fed raw (HW tf32 truncation).
//  - sigma k-permutation on both operands: logical (t,t+4) = phys (2t,2t+1).
// ============================================================================

#define BATCH   32768
#define IN_DIM  1024
#define OUT_DIM 1024

#define BM 128
#define BN 128
#define KC 32
#define NCHUNK (IN_DIM / KC)            // 32
#define NST 3

#define TILE_BYTES  16384               // A: 128 rows x 128 B
#define SMEM_TOTAL  (NST * TILE_BYTES)  // 49152 B -> 2 CTAs/SM easily

// W, RNA-rounded to tf32
__device__ float g_W[(size_t)OUT_DIM * IN_DIM];   // 4 MB static scratch

// ---------------------------------------------------------------- helpers
__device__ __forceinline__ void cp16(uint32_t dst, const void* src) {
    asm volatile("cp.async.cg.shared.global [%0], [%1], 16;"
                 :: "r"(dst), "l"(src));
}
#define CP_COMMIT() asm volatile("cp.async.commit_group;" ::: "memory")
#define CP_WAIT_1() asm volatile("cp.async.wait_group 1;" ::: "memory")

__device__ __forceinline__ uint32_t smem_u32(const void* p) {
    uint32_t a;
    asm("{ .reg .u64 t; cvta.to.shared.u64 t, %1; cvt.u32.u64 %0, t; }"
        : "=r"(a) : "l"(p));
    return a;
}

// unbiased fp32 -> tf32 (round-to-nearest-away)
__device__ __forceinline__ float f2tf(float x) {
    uint32_t r;
    asm("cvt.rna.tf32.f32 %0, %1;" : "=r"(r) : "f"(x));
    return __uint_as_float(r);
}

__device__ __forceinline__ void mma8(float* c,
                                     uint32_t a0, uint32_t a1, uint32_t a2, uint32_t a3,
                                     uint32_t b0, uint32_t b1) {
    asm volatile(
        "mma.sync.aligned.m16n8k8.row.col.f32.tf32.tf32.f32 "
        "{%0,%1,%2,%3}, {%4,%5,%6,%7}, {%8,%9}, {%0,%1,%2,%3};"
        : "+f"(c[0]), "+f"(c[1]), "+f"(c[2]), "+f"(c[3])
        : "r"(a0), "r"(a1), "r"(a2), "r"(a3), "r"(b0), "r"(b1));
}

// ---------------------------------------------------------------- W prep
__global__ void __launch_bounds__(256) prep_W_kernel(const float4* __restrict__ src) {
    const int i = blockIdx.x * blockDim.x + threadIdx.x;
    float4 v = src[i];
    v.x = f2tf(v.x); v.y = f2tf(v.y); v.z = f2tf(v.z); v.w = f2tf(v.w);
    reinterpret_cast<float4*>(g_W)[i] = v;
}

// ---------------------------------------------------------------- GEMM
// grid = 256 * 8 = 2048 CTAs, 128 threads. nt inner: 8 CTAs share an A stripe.
extern "C" __global__ void __launch_bounds__(128, 2)
groupfc_tf32_kernel(const float* __restrict__ A, const float* __restrict__ bias,
                    float* __restrict__ out) {
    extern __shared__ char smem[];
    const uint32_t sb = smem_u32(smem);

    const int tid  = threadIdx.x;
    const int wid  = tid >> 5;       // warp owns cols wid*32 .. wid*32+31
    const int lane = tid & 31;
    const int g    = lane >> 2;
    const int t    = lane & 3;

    const int mt = blockIdx.x >> 3;
    const int nt = blockIdx.x & 7;
    const int m0 = mt * BM;
    const int n0 = nt * BN;

    // A staging: thread fills 16B chunk ech of rows erow+16i (i<8).
    // 32B-granular swizzle: off = row*128 + (((ech>>1) ^ (row&3))<<5) + (ech&1)*16
    const int erow = tid >> 3;
    const int ech  = tid & 7;
    const uint32_t swz = (uint32_t)((((ech >> 1) ^ (erow & 3)) << 5) + ((ech & 1) << 4));
    const float* gA = A + (size_t)(m0 + erow) * IN_DIM + ech * 4;
    const uint32_t sdA = sb + (uint32_t)erow * 128 + swz;

    // B base: row = n0 + wid*32 + g (+ni*8), k low bits: +2t (sigma)
    const float* wbase = g_W + (size_t)(n0 + wid * 32 + g) * IN_DIM + 2 * t;

    float c[8][4][4];
#pragma unroll
    for (int mi = 0; mi < 8; mi++)
#pragma unroll
        for (int ni = 0; ni < 4; ni++)
#pragma unroll
            for (int j = 0; j < 4; j++) c[mi][ni][j] = 0.0f;

#define FILL(cc, s)                                                           \
    do {                                                                      \
        const uint32_t _o = sdA + (uint32_t)(s) * TILE_BYTES;                 \
        const float* _pa = gA + (size_t)(cc) * KC;                            \
        _Pragma("unroll")                                                     \
        for (int _i = 0; _i < 8; _i++)                                        \
            cp16(_o + _i * 16 * 128, _pa + (size_t)_i * 16 * IN_DIM);         \
    } while (0)

    // whole-chunk B prefetch into registers: dst[ks][ni], uint2 each
#define LOADB(dst, cc_)                                                       \
    do {                                                                      \
        const float* _wb = wbase + (size_t)(cc_) * KC;                        \
        _Pragma("unroll")                                                     \
        for (int _ks = 0; _ks < 4; _ks++)                                     \
            _Pragma("unroll")                                                 \
            for (int _ni = 0; _ni < 4; _ni++)                                 \
                dst[_ks][_ni] = __ldg(reinterpret_cast<const uint2*>(         \
                    _wb + (size_t)_ni * 8 * IN_DIM + _ks * 8));               \
    } while (0)

    // one chunk of compute: uses BCUR, prefetches BNEXT for chunk cc+1
#define CHUNK_BODY(cc, BCUR, BNEXT)                                           \
    do {                                                                      \
        CP_WAIT_1();                                                          \
        __syncthreads();                                                      \
        if ((cc) + 1 < NCHUNK) LOADB(BNEXT, (cc) + 1);                        \
        const char* pa = smem + (size_t)((cc) % NST) * TILE_BYTES;            \
        _Pragma("unroll")                                                     \
        for (int ks = 0; ks < 4; ks++) {                                      \
            const int xsw = ((ks ^ (g & 3)) << 5) + t * 8;                    \
            _Pragma("unroll")                                                 \
            for (int mi = 0; mi < 8; mi++) {                                  \
                const char* r0 = pa + (size_t)(mi * 16 + g) * 128 + xsw;      \
                uint2 lo = *(const uint2*)(r0);                               \
                uint2 hi = *(const uint2*)(r0 + 8 * 128);                     \
                _Pragma("unroll")                                             \
                for (int ni = 0; ni < 4; ni++)                                \
                    mma8(c[mi][ni], lo.x, hi.x, lo.y, hi.y,                   \
                         BCUR[ks][ni].x, BCUR[ks][ni].y);                     \
            }                                                                 \
        }                                                                     \
        if ((cc) + 2 < NCHUNK) { FILL((cc) + 2, ((cc) + 2) % NST); }          \
        CP_COMMIT();                                                          \
    } while (0)

    uint2 bu0[4][4], bu1[4][4];

    FILL(0, 0); CP_COMMIT();
    FILL(1, 1); CP_COMMIT();
    LOADB(bu0, 0);

#pragma unroll 1
    for (int cp = 0; cp < NCHUNK / 2; cp++) {
        CHUNK_BODY(2 * cp,     bu0, bu1);
        CHUNK_BODY(2 * cp + 1, bu1, bu0);
    }

    // ---- epilogue: bias add + float2 stores
#pragma unroll
    for (int mi = 0; mi < 8; mi++) {
        const int r = m0 + mi * 16 + g;
        float* o0 = out + (size_t)r * OUT_DIM + n0 + wid * 32 + 2 * t;
        float* o1 = o0 + 8 * OUT_DIM;
#pragma unroll
        for (int ni = 0; ni < 4; ni++) {
            const int col = n0 + wid * 32 + ni * 8 + 2 * t;
            const float b0v = __ldg(bias + col);
            const float b1v = __ldg(bias + col + 1);
            *(float2*)(o0 + ni * 8) = make_float2(c[mi][ni][0] + b0v, c[mi][ni][1] + b1v);
            *(float2*)(o1 + ni * 8) = make_float2(c[mi][ni][2] + b0v, c[mi][ni][3] + b1v);
        }
    }
}

// ---------------------------------------------------------------- launch
extern "C" void kernel_launch(void* const* d_in, const int* in_sizes, int n_in,
                              void* d_out, int out_size) {
    const float* A    = (const float*)d_in[0];
    const float* W    = (const float*)d_in[1];
    const float* bias = (const float*)d_in[2];
    float* out = (float*)d_out;
    (void)in_sizes; (void)n_in; (void)out_size;

    cudaFuncSetAttribute(groupfc_tf32_kernel,
                         cudaFuncAttributeMaxDynamicSharedMemorySize, SMEM_TOTAL);

    prep_W_kernel<<<1024, 256>>>(reinterpret_cast<const float4*>(W));

    const int grid = (BATCH / BM) * (OUT_DIM / BN);  // 2048
    groupfc_tf32_kernel<<<grid, 128, SMEM_TOTAL>>>(A, bias, out);
}

// round 10
// speedup vs baseline: 1.1216x; 1.1216x over previous
#include <cuda_runtime.h>
#include <cstdint>

// ============================================================================
// GroupFC: out[32768,1024] = data @ W^T + b (fp32), mma.sync tf32 (sm_103).
// R10: R8 + LDS.128 fragment feeding.
//  - k16-group layout: thread t owns phys k {16G+4t..16G+4t+3} as one 16B unit;
//    one LDS.128 feeds two k-slices (words xy / zw). Same-sigma on A and B.
//  - parity swizzle: unit u of row r stored at col u ^ ((r&1)<<2)
//    -> conflict-free LDS.128 (phases of 8 rows x 8 distinct cols) and
//       conflict-free cp.async stores (phase = one full row).
//  - A fed raw (HW tf32 truncate), W RNA-pre-rounded (rel_err 4.56e-4, proven).
//  - 3-stage cp.async, wait_group 1, 2 CTAs/SM (R8 skeleton).
// ============================================================================

#define BATCH   32768
#define IN_DIM  1024
#define OUT_DIM 1024

#define BM 128
#define BN 128
#define KC 32
#define NCHUNK (IN_DIM / KC)            // 32
#define NST 3

#define TILE_BYTES  16384               // 128 rows x 128 B
#define STAGE_BYTES (2 * TILE_BYTES)    // A tile + B tile
#define SMEM_TOTAL  (NST * STAGE_BYTES) // 98304 B -> 2 CTAs/SM

// W, RNA-rounded to tf32
__device__ float g_W[(size_t)OUT_DIM * IN_DIM];   // 4 MB static scratch

// ---------------------------------------------------------------- helpers
__device__ __forceinline__ void cp16(uint32_t dst, const void* src) {
    asm volatile("cp.async.cg.shared.global [%0], [%1], 16;"
                 :: "r"(dst), "l"(src));
}
#define CP_COMMIT() asm volatile("cp.async.commit_group;" ::: "memory")
#define CP_WAIT_1() asm volatile("cp.async.wait_group 1;" ::: "memory")

__device__ __forceinline__ uint32_t smem_u32(const void* p) {
    uint32_t a;
    asm("{ .reg .u64 t; cvta.to.shared.u64 t, %1; cvt.u32.u64 %0, t; }"
        : "=r"(a) : "l"(p));
    return a;
}

// unbiased fp32 -> tf32 (round-to-nearest-away)
__device__ __forceinline__ float f2tf(float x) {
    uint32_t r;
    asm("cvt.rna.tf32.f32 %0, %1;" : "=r"(r) : "f"(x));
    return __uint_as_float(r);
}

__device__ __forceinline__ void mma8(float* c,
                                     uint32_t a0, uint32_t a1, uint32_t a2, uint32_t a3,
                                     uint32_t b0, uint32_t b1) {
    asm volatile(
        "mma.sync.aligned.m16n8k8.row.col.f32.tf32.tf32.f32 "
        "{%0,%1,%2,%3}, {%4,%5,%6,%7}, {%8,%9}, {%0,%1,%2,%3};"
        : "+f"(c[0]), "+f"(c[1]), "+f"(c[2]), "+f"(c[3])
        : "r"(a0), "r"(a1), "r"(a2), "r"(a3), "r"(b0), "r"(b1));
}

// ---------------------------------------------------------------- W prep
__global__ void __launch_bounds__(256) prep_W_kernel(const float4* __restrict__ src) {
    const int i = blockIdx.x * blockDim.x + threadIdx.x;
    float4 v = src[i];
    v.x = f2tf(v.x); v.y = f2tf(v.y); v.z = f2tf(v.z); v.w = f2tf(v.w);
    reinterpret_cast<float4*>(g_W)[i] = v;
}

// ---------------------------------------------------------------- GEMM
// grid = 256 * 8 = 2048 CTAs, 128 threads. nt inner: 8 CTAs share an A stripe.
extern "C" __global__ void __launch_bounds__(128, 2)
groupfc_tf32_kernel(const float* __restrict__ A, const float* __restrict__ bias,
                    float* __restrict__ out) {
    extern __shared__ char smem[];
    const uint32_t sb = smem_u32(smem);

    const int tid  = threadIdx.x;
    const int wid  = tid >> 5;
    const int lane = tid & 31;
    const int g    = lane >> 2;
    const int t    = lane & 3;
    const int wm   = wid >> 1;
    const int wn   = wid & 1;

    const int mt = blockIdx.x >> 3;
    const int nt = blockIdx.x & 7;
    const int m0 = mt * BM;
    const int n0 = nt * BN;

    // staging: thread fills 16B unit ech of rows erow+16i (i<8).
    // parity swizzle: col = ech ^ ((erow&1)<<2)
    //   byte off = ((ech>>2) ^ (erow&1))*64 + (ech&3)*16   (const per thread)
    const int erow = tid >> 3;
    const int ech  = tid & 7;
    const uint32_t swz = (uint32_t)(((((ech >> 2) ^ (erow & 1))) << 6) + ((ech & 3) << 4));
    const float* gA = A + (size_t)(m0 + erow) * IN_DIM + ech * 4;
    const float* gW = g_W + (size_t)(n0 + erow) * IN_DIM + ech * 4;
    const uint32_t sdA = sb + (uint32_t)erow * 128 + swz;
    const uint32_t sdB = sdA + TILE_BYTES;

    float c[4][8][4];
#pragma unroll
    for (int mi = 0; mi < 4; mi++)
#pragma unroll
        for (int ni = 0; ni < 8; ni++)
#pragma unroll
            for (int j = 0; j < 4; j++) c[mi][ni][j] = 0.0f;

#define FILL(cc, s)                                                           \
    do {                                                                      \
        const uint32_t _o = (uint32_t)(s) * STAGE_BYTES;                      \
        const float* _pa = gA + (size_t)(cc) * KC;                            \
        const float* _pw = gW + (size_t)(cc) * KC;                            \
        _Pragma("unroll")                                                     \
        for (int _i = 0; _i < 8; _i++) {                                      \
            cp16(sdA + _o + _i * 16 * 128, _pa + (size_t)_i * 16 * IN_DIM);   \
            cp16(sdB + _o + _i * 16 * 128, _pw + (size_t)_i * 16 * IN_DIM);   \
        }                                                                     \
    } while (0)

    FILL(0, 0); CP_COMMIT();
    FILL(1, 1); CP_COMMIT();

    const int arow0 = wm * 64 + g;
    const int brow0 = wn * 64 + g;

#pragma unroll 1
    for (int cc = 0; cc < NCHUNK; cc++) {
        CP_WAIT_1();
        __syncthreads();

        const int s = cc % NST;
        const char* pa = smem + (size_t)s * STAGE_BYTES;
        const char* pb = pa + TILE_BYTES;

#pragma unroll
        for (int G = 0; G < 2; G++) {   // two k16 groups per chunk
            // thread t's 16B unit for group G: byte (G^(g&1))*64 + t*16
            const int cby = ((G ^ (g & 1)) << 6) + (t << 4);

            // B: one LDS.128 per ni covers both sub-slices
            uint4 b[8];
#pragma unroll
            for (int ni = 0; ni < 8; ni++)
                b[ni] = *(const uint4*)(pb + (size_t)(brow0 + ni * 8) * 128 + cby);

#pragma unroll
            for (int mi = 0; mi < 4; mi++) {
                const char* r0 = pa + (size_t)(arow0 + mi * 16) * 128 + cby;
                uint4 lo = *(const uint4*)(r0);             // row g
                uint4 hi = *(const uint4*)(r0 + 8 * 128);   // row g+8
                // sub-slice 0: phys k = 16G+4t, 16G+4t+1
#pragma unroll
                for (int ni = 0; ni < 8; ni++)
                    mma8(c[mi][ni], lo.x, hi.x, lo.y, hi.y, b[ni].x, b[ni].y);
                // sub-slice 1: phys k = 16G+4t+2, 16G+4t+3
#pragma unroll
                for (int ni = 0; ni < 8; ni++)
                    mma8(c[mi][ni], lo.z, hi.z, lo.w, hi.w, b[ni].z, b[ni].w);
            }
        }

        if (cc + 2 < NCHUNK) { FILL(cc + 2, (cc + 2) % NST); }
        CP_COMMIT();
    }

    // ---- epilogue: bias add + float2 stores
#pragma unroll
    for (int mi = 0; mi < 4; mi++) {
        const int r = m0 + wm * 64 + mi * 16 + g;
        float* o0 = out + (size_t)r * OUT_DIM + n0 + wn * 64 + 2 * t;
        float* o1 = o0 + 8 * OUT_DIM;
#pragma unroll
        for (int ni = 0; ni < 8; ni++) {
            const int col = n0 + wn * 64 + ni * 8 + 2 * t;
            const float b0v = __ldg(bias + col);
            const float b1v = __ldg(bias + col + 1);
            *(float2*)(o0 + ni * 8) = make_float2(c[mi][ni][0] + b0v, c[mi][ni][1] + b1v);
            *(float2*)(o1 + ni * 8) = make_float2(c[mi][ni][2] + b0v, c[mi][ni][3] + b1v);
        }
    }
}

// ---------------------------------------------------------------- launch
extern "C" void kernel_launch(void* const* d_in, const int* in_sizes, int n_in,
                              void* d_out, int out_size) {
    const float* A    = (const float*)d_in[0];
    const float* W    = (const float*)d_in[1];
    const float* bias = (const float*)d_in[2];
    float* out = (float*)d_out;
    (void)in_sizes; (void)n_in; (void)out_size;

    cudaFuncSetAttribute(groupfc_tf32_kernel,
                         cudaFuncAttributeMaxDynamicSharedMemorySize, SMEM_TOTAL);

    prep_W_kernel<<<1024, 256>>>(reinterpret_cast<const float4*>(W));

    const int grid = (BATCH / BM) * (OUT_DIM / BN);  // 2048
    groupfc_tf32_kernel<<<grid, 128, SMEM_TOTAL>>>(A, bias, out);
}

// round 11
// speedup vs baseline: 1.8498x; 1.6493x over previous
#include <cuda_runtime.h>
#include <cuda_fp16.h>
#include <cstdint>

// ============================================================================
// GroupFC: out[32768,1024] = data @ W^T + b (fp32), sm_103-compatible.
// R11: fp16 m16n8k16 MMA (same 10-bit mantissa as tf32, 2x K/instr ->
//      tensor-busy floor halves 228->114us). Both operands pre-converted RN
//      (unbiased, rel_err ~2.8e-4 expected, = R2/R3 structure).
//      R8 skeleton: 3-stage cp.async (wait_group 1), 32B-granular swizzle,
//      conflict-free LDS.64 fragment feed, sigma k-order on both operands.
//      KC=64 fp16 k per chunk = same 128B rows, 16 chunks (half the syncs).
// ============================================================================

#define BATCH   32768
#define IN_DIM  1024
#define OUT_DIM 1024

#define BM 128
#define BN 128
#define KC 64                           // fp16 k per chunk (128 B per row)
#define NCHUNK (IN_DIM / KC)            // 16
#define NST 3

#define TILE_BYTES  16384               // 128 rows x 128 B
#define STAGE_BYTES (2 * TILE_BYTES)    // A tile + B tile
#define SMEM_TOTAL  (NST * STAGE_BYTES) // 98304 B -> 2 CTAs/SM

// fp16 copies (RN-rounded), static device scratch
__device__ __half g_Ah[(size_t)BATCH * IN_DIM];    // 64 MB
__device__ __half g_Wh[(size_t)OUT_DIM * IN_DIM];  // 2 MB

// ---------------------------------------------------------------- helpers
__device__ __forceinline__ void cp16(uint32_t dst, const void* src) {
    asm volatile("cp.async.cg.shared.global [%0], [%1], 16;"
                 :: "r"(dst), "l"(src));
}
#define CP_COMMIT() asm volatile("cp.async.commit_group;" ::: "memory")
#define CP_WAIT_1() asm volatile("cp.async.wait_group 1;" ::: "memory")

__device__ __forceinline__ uint32_t smem_u32(const void* p) {
    uint32_t a;
    asm("{ .reg .u64 t; cvta.to.shared.u64 t, %1; cvt.u32.u64 %0, t; }"
        : "=r"(a) : "l"(p));
    return a;
}

__device__ __forceinline__ void mma16(float* c,
                                      uint32_t a0, uint32_t a1, uint32_t a2, uint32_t a3,
                                      uint32_t b0, uint32_t b1) {
    asm volatile(
        "mma.sync.aligned.m16n8k16.row.col.f32.f16.f16.f32 "
        "{%0,%1,%2,%3}, {%4,%5,%6,%7}, {%8,%9}, {%0,%1,%2,%3};"
        : "+f"(c[0]), "+f"(c[1]), "+f"(c[2]), "+f"(c[3])
        : "r"(a0), "r"(a1), "r"(a2), "r"(a3), "r"(b0), "r"(b1));
}

// ---------------------------------------------------------------- prep
// fp32 -> fp16 (RN). Each thread converts 8 elements (2x float4 -> 1x uint4).
__device__ __forceinline__ void cvt8(const float4* __restrict__ src,
                                     uint4* __restrict__ dst, size_t i8) {
    float4 v0 = src[i8 * 2];
    float4 v1 = src[i8 * 2 + 1];
    __half2 h0 = __float22half2_rn(make_float2(v0.x, v0.y));
    __half2 h1 = __float22half2_rn(make_float2(v0.z, v0.w));
    __half2 h2 = __float22half2_rn(make_float2(v1.x, v1.y));
    __half2 h3 = __float22half2_rn(make_float2(v1.z, v1.w));
    uint4 o;
    o.x = *reinterpret_cast<uint32_t*>(&h0);
    o.y = *reinterpret_cast<uint32_t*>(&h1);
    o.z = *reinterpret_cast<uint32_t*>(&h2);
    o.w = *reinterpret_cast<uint32_t*>(&h3);
    dst[i8] = o;
}

__global__ void __launch_bounds__(256) prep_A_kernel(const float4* __restrict__ src) {
    const size_t i8 = (size_t)blockIdx.x * blockDim.x + threadIdx.x;
    cvt8(src, reinterpret_cast<uint4*>(g_Ah), i8);
}
__global__ void __launch_bounds__(256) prep_W_kernel(const float4* __restrict__ src) {
    const size_t i8 = (size_t)blockIdx.x * blockDim.x + threadIdx.x;
    cvt8(src, reinterpret_cast<uint4*>(g_Wh), i8);
}

// ---------------------------------------------------------------- GEMM
// grid = 256 * 8 = 2048 CTAs, 128 threads. nt inner: 8 CTAs share an A stripe.
extern "C" __global__ void __launch_bounds__(128, 2)
groupfc_f16_kernel(const float* __restrict__ bias, float* __restrict__ out) {
    extern __shared__ char smem[];
    const uint32_t sb = smem_u32(smem);

    const int tid  = threadIdx.x;
    const int wid  = tid >> 5;
    const int lane = tid & 31;
    const int g    = lane >> 2;
    const int t    = lane & 3;
    const int wm   = wid >> 1;
    const int wn   = wid & 1;

    const int mt = blockIdx.x >> 3;
    const int nt = blockIdx.x & 7;
    const int m0 = mt * BM;
    const int n0 = nt * BN;

    // staging: thread fills 16B chunk ech of rows erow+16i (i<8).
    // 32B-granular swizzle: off = row*128 + (((ech>>1) ^ (row&3))<<5) + (ech&1)*16
    const int erow = tid >> 3;
    const int ech  = tid & 7;
    const uint32_t swz = (uint32_t)((((ech >> 1) ^ (erow & 3)) << 5) + ((ech & 1) << 4));
    const __half* gA = g_Ah + (size_t)(m0 + erow) * IN_DIM + ech * 8;
    const __half* gW = g_Wh + (size_t)(n0 + erow) * IN_DIM + ech * 8;
    const uint32_t sdA = sb + (uint32_t)erow * 128 + swz;
    const uint32_t sdB = sdA + TILE_BYTES;

    float c[4][8][4];
#pragma unroll
    for (int mi = 0; mi < 4; mi++)
#pragma unroll
        for (int ni = 0; ni < 8; ni++)
#pragma unroll
            for (int j = 0; j < 4; j++) c[mi][ni][j] = 0.0f;

#define FILL(cc, s)                                                           \
    do {                                                                      \
        const uint32_t _o = (uint32_t)(s) * STAGE_BYTES;                      \
        const __half* _pa = gA + (size_t)(cc) * KC;                           \
        const __half* _pw = gW + (size_t)(cc) * KC;                           \
        _Pragma("unroll")                                                     \
        for (int _i = 0; _i < 8; _i++) {                                      \
            cp16(sdA + _o + _i * 16 * 128, _pa + (size_t)_i * 16 * IN_DIM);   \
            cp16(sdB + _o + _i * 16 * 128, _pw + (size_t)_i * 16 * IN_DIM);   \
        }                                                                     \
    } while (0)

    FILL(0, 0); CP_COMMIT();
    FILL(1, 1); CP_COMMIT();

    const int arow0 = wm * 64 + g;      // (row & 3) == (g & 3) for all offsets
    const int brow0 = wn * 64 + g;

#pragma unroll 1
    for (int cc = 0; cc < NCHUNK; cc++) {
        CP_WAIT_1();
        __syncthreads();

        const int s = cc % NST;
        const char* pa = smem + (size_t)s * STAGE_BYTES;
        const char* pb = pa + TILE_BYTES;

#pragma unroll
        for (int ks = 0; ks < 4; ks++) {
            // kslice = 16 fp16 k = one 32B chunk. sigma: thread t owns phys
            // fp16 k {16ks+4t .. 16ks+4t+3} as one 8B unit:
            //   uint2.x = (a0|b0) = logical k 2t,2t+1 ; .y = (a2|b1) = k 8+2t,+1
            const int xsw = ((ks ^ (g & 3)) << 5) + t * 8;

            // B: one conflict-free LDS.64 per ni
            uint2 b[8];
#pragma unroll
            for (int ni = 0; ni < 8; ni++)
                b[ni] = *(const uint2*)(pb + (size_t)(brow0 + ni * 8) * 128 + xsw);

            // A: two conflict-free LDS.64 per mi
#pragma unroll
            for (int mi = 0; mi < 4; mi++) {
                const char* r0 = pa + (size_t)(arow0 + mi * 16) * 128 + xsw;
                uint2 lo = *(const uint2*)(r0);             // row g:   a0, a2
                uint2 hi = *(const uint2*)(r0 + 8 * 128);   // row g+8: a1, a3
#pragma unroll
                for (int ni = 0; ni < 8; ni++)
                    mma16(c[mi][ni], lo.x, hi.x, lo.y, hi.y, b[ni].x, b[ni].y);
            }
        }

        if (cc + 2 < NCHUNK) { FILL(cc + 2, (cc + 2) % NST); }
        CP_COMMIT();
    }

    // ---- epilogue: bias add + float2 stores
#pragma unroll
    for (int mi = 0; mi < 4; mi++) {
        const int r = m0 + wm * 64 + mi * 16 + g;
        float* o0 = out + (size_t)r * OUT_DIM + n0 + wn * 64 + 2 * t;
        float* o1 = o0 + 8 * OUT_DIM;
#pragma unroll
        for (int ni = 0; ni < 8; ni++) {
            const int col = n0 + wn * 64 + ni * 8 + 2 * t;
            const float b0v = __ldg(bias + col);
            const float b1v = __ldg(bias + col + 1);
            *(float2*)(o0 + ni * 8) = make_float2(c[mi][ni][0] + b0v, c[mi][ni][1] + b1v);
            *(float2*)(o1 + ni * 8) = make_float2(c[mi][ni][2] + b0v, c[mi][ni][3] + b1v);
        }
    }
}

// ---------------------------------------------------------------- launch
extern "C" void kernel_launch(void* const* d_in, const int* in_sizes, int n_in,
                              void* d_out, int out_size) {
    const float* A    = (const float*)d_in[0];
    const float* W    = (const float*)d_in[1];
    const float* bias = (const float*)d_in[2];
    float* out = (float*)d_out;
    (void)in_sizes; (void)n_in; (void)out_size;

    cudaFuncSetAttribute(groupfc_f16_kernel,
                         cudaFuncAttributeMaxDynamicSharedMemorySize, SMEM_TOTAL);

    // A: 32M elems / 8 per thread / 256 thr = 16384 blocks
    prep_A_kernel<<<16384, 256>>>(reinterpret_cast<const float4*>(A));
    // W: 1M elems / 8 / 256 = 512 blocks
    prep_W_kernel<<<512, 256>>>(reinterpret_cast<const float4*>(W));

    const int grid = (BATCH / BM) * (OUT_DIM / BN);  // 2048
    groupfc_f16_kernel<<<grid, 128, SMEM_TOTAL>>>(bias, out);
}